// round 9
// baseline (speedup 1.0000x reference)
#include <cuda_runtime.h>

#define NF    22528          // NUM_FEATURES
#define NOUT  520            // HIDDEN + BUCKET_NB
#define HID   512
#define NROWS 8192
#define NB    8
#define MAXIDX 512
#define SCALE_O 400.0f
#define NSTAGES 22           // 22 chunks of 1024 floats = 22528

// Transposed feature-transform weights: W_ftT[f][o] = W_ft[o][f]. 46.9 MB.
__device__ float g_WftT[(size_t)NF * NOUT];

// ---------------------------------------------------------------------------
// Kernel 0: transpose W_ft [520, 22528] -> g_WftT [22528, 520]
// ---------------------------------------------------------------------------
__global__ void transpose_wft(const float* __restrict__ W) {
    __shared__ float tile[32][33];
    int f0 = blockIdx.x * 32;
    int o0 = blockIdx.y * 32;
    int tx = threadIdx.x;   // 0..31
    int ty = threadIdx.y;   // 0..7
#pragma unroll
    for (int i = 0; i < 4; i++) {
        int o = o0 + ty + 8 * i;
        float v = 0.0f;
        if (o < NOUT) v = W[(size_t)o * NF + f0 + tx];
        tile[ty + 8 * i][tx] = v;
    }
    __syncthreads();
#pragma unroll
    for (int i = 0; i < 4; i++) {
        int f = f0 + ty + 8 * i;
        int o = o0 + tx;
        if (o < NOUT)
            g_WftT[(size_t)f * NOUT + o] = tile[tx][ty + 8 * i];
    }
}

// ---------------------------------------------------------------------------
// cp.async helpers (plain form — no cache-policy operand)
// ---------------------------------------------------------------------------
__device__ __forceinline__ void cp16(void* smem, const void* gmem) {
    unsigned sa = (unsigned)__cvta_generic_to_shared(smem);
    asm volatile("cp.async.cg.shared.global [%0], [%1], 16;"
                 :: "r"(sa), "l"(gmem));
}
__device__ __forceinline__ void cp_commit() {
    asm volatile("cp.async.commit_group;");
}
template <int N>
__device__ __forceinline__ void cp_wait() {
    asm volatile("cp.async.wait_group %0;" :: "n"(N));
}

// ---------------------------------------------------------------------------
// Main kernel: one block per batch row
// ---------------------------------------------------------------------------
__device__ __forceinline__ float clip01(float v) {
    return fminf(fmaxf(v, 0.0f), 1.0f);
}

__global__ __launch_bounds__(256, 8) void nnue_row(
    const float* __restrict__ wf,      // [8192, 22528]
    const float* __restrict__ bfeat,   // [8192, 22528]
    const float* __restrict__ stm_arr, // [8192, 1]
    const int*   __restrict__ buckets, // [8192]
    const float* __restrict__ b_ft,    // [520]
    const float* __restrict__ W1,      // [8, 32, 1024]
    const float* __restrict__ b1,      // [8, 32]
    const float* __restrict__ W2,      // [8, 32, 32]
    const float* __restrict__ b2,      // [8, 32]
    const float* __restrict__ W3,      // [8, 1, 32]
    const float* __restrict__ b3,      // [8, 1]
    float*       __restrict__ out)     // [8192]
{
    __shared__ uint4 s_buf[2][2][256];    // [parity][w/b][thread] : 16 KB
    __shared__ int   s_idxW[MAXIDX];
    __shared__ int   s_idxB[MAXIDX];
    __shared__ int   s_cntW, s_cntB;
    __shared__ float s_x[1024];
    __shared__ float s_h1[32];

    const int row = blockIdx.x;
    const int tid = threadIdx.x;

    const uint4* w4 = (const uint4*)(wf    + (size_t)row * NF);   // 5632 uint4
    const uint4* b4 = (const uint4*)(bfeat + (size_t)row * NF);

    // prologue: issue stage 0 immediately
    cp16(&s_buf[0][0][tid], w4 + tid);
    cp16(&s_buf[0][1][tid], b4 + tid);
    cp_commit();

    if (tid == 0) { s_cntW = 0; s_cntB = 0; }
    __syncthreads();

    // ---- Phase A: cp.async double-buffered scan (features are exact 0.0/1.0) ----
    for (int s = 0; s < NSTAGES; s++) {
        if (s + 1 < NSTAGES) {
            cp16(&s_buf[(s + 1) & 1][0][tid], w4 + (s + 1) * 256 + tid);
            cp16(&s_buf[(s + 1) & 1][1][tid], b4 + (s + 1) * 256 + tid);
            cp_commit();
            cp_wait<1>();
        } else {
            cp_wait<0>();
        }
        __syncthreads();

        uint4 v = s_buf[s & 1][0][tid];
        uint4 q = s_buf[s & 1][1][tid];
        const int base = s * 1024 + 4 * tid;
        if (v.x | v.y | v.z | v.w) {
            if (v.x) { int p = atomicAdd(&s_cntW, 1); if (p < MAXIDX) s_idxW[p] = base + 0; }
            if (v.y) { int p = atomicAdd(&s_cntW, 1); if (p < MAXIDX) s_idxW[p] = base + 1; }
            if (v.z) { int p = atomicAdd(&s_cntW, 1); if (p < MAXIDX) s_idxW[p] = base + 2; }
            if (v.w) { int p = atomicAdd(&s_cntW, 1); if (p < MAXIDX) s_idxW[p] = base + 3; }
        }
        if (q.x | q.y | q.z | q.w) {
            if (q.x) { int p = atomicAdd(&s_cntB, 1); if (p < MAXIDX) s_idxB[p] = base + 0; }
            if (q.y) { int p = atomicAdd(&s_cntB, 1); if (p < MAXIDX) s_idxB[p] = base + 1; }
            if (q.z) { int p = atomicAdd(&s_cntB, 1); if (p < MAXIDX) s_idxB[p] = base + 2; }
            if (q.w) { int p = atomicAdd(&s_cntB, 1); if (p < MAXIDX) s_idxB[p] = base + 3; }
        }
        __syncthreads();   // buffer s&1 reused at iteration s+1's issue
    }
    const int cw = min(s_cntW, MAXIDX);
    const int cb = min(s_cntB, MAXIDX);
    const int k  = buckets[row];

    // ---- Phase B: register accumulators; float2 gather (thread t: cols 2t,2t+1)
    float2 aw = *(const float2*)(b_ft + 2 * tid);
    float2 ab = aw;
    float psw = 0.0f, psb = 0.0f;   // b_ft cancels in the psqt difference

#pragma unroll 4
    for (int i = 0; i < cw; i++) {
        const float* r = g_WftT + (size_t)s_idxW[i] * NOUT;
        float2 v = *(const float2*)(r + 2 * tid);
        aw.x += v.x; aw.y += v.y;
        if (tid == 0) psw += r[512 + k];
    }
#pragma unroll 4
    for (int i = 0; i < cb; i++) {
        const float* r = g_WftT + (size_t)s_idxB[i] * NOUT;
        float2 v = *(const float2*)(r + 2 * tid);
        ab.x += v.x; ab.y += v.y;
        if (tid == 0) psb += r[512 + k];
    }

    // ---- Phase C: stm-ordered clip into x[1024] ----
    const float stm = stm_arr[row];   // exactly 0.0 or 1.0
    const bool wfirst = (stm == 0.0f);
    float2 xf = wfirst ? aw : ab;
    float2 xs = wfirst ? ab : aw;

    float2* x2 = (float2*)s_x;
    x2[tid]       = make_float2(clip01(xf.x), clip01(xf.y));
    x2[256 + tid] = make_float2(clip01(xs.x), clip01(xs.y));
    __syncthreads();

    // ---- Layer 1: warp w computes outputs 4w..4w+3 (float2 dot) ----
    const int warp = tid >> 5, lane = tid & 31;
    const float2* W1k = (const float2*)(W1 + (size_t)k * 32 * 1024);
    const float2* sx2 = (const float2*)s_x;
#pragma unroll
    for (int oo = 0; oo < 4; oo++) {
        const int o = warp * 4 + oo;
        const float2* wr = W1k + o * 512;
        float s = 0.0f;
#pragma unroll
        for (int m = 0; m < 16; m++) {
            float2 xv = sx2[lane + 32 * m];          // conflict-free
            float2 wv = __ldg(&wr[lane + 32 * m]);
            s += xv.x * wv.x + xv.y * wv.y;
        }
#pragma unroll
        for (int d = 16; d; d >>= 1) s += __shfl_xor_sync(0xFFFFFFFFu, s, d);
        if (lane == 0) s_h1[o] = clip01(s + __ldg(&b1[k * 32 + o]));
    }
    __syncthreads();

    // ---- Layers 2+3 + psqt + output: warp 0 ----
    if (warp == 0) {
        const float* W2k = W2 + k * 32 * 32;
        float s = 0.0f;
#pragma unroll
        for (int i = 0; i < 32; i++)
            s += s_h1[i] * __ldg(&W2k[lane * 32 + i]);
        float h2 = clip01(s + __ldg(&b2[k * 32 + lane]));

        float p = h2 * __ldg(&W3[k * 32 + lane]);
#pragma unroll
        for (int d = 16; d; d >>= 1) p += __shfl_xor_sync(0xFFFFFFFFu, p, d);

        if (lane == 0) {
            float psqt = (psw - psb) * (0.5f - stm);
            out[row] = (p + __ldg(&b3[k]) + psqt) * SCALE_O;
        }
    }
}

// ---------------------------------------------------------------------------
// Harness entry
// ---------------------------------------------------------------------------
extern "C" void kernel_launch(void* const* d_in, const int* in_sizes, int n_in,
                              void* d_out, int out_size) {
    const float* wf    = (const float*)d_in[0];
    const float* bfeat = (const float*)d_in[1];
    const float* stm   = (const float*)d_in[2];
    const int*   bkt   = (const int*)  d_in[3];
    const float* W_ft  = (const float*)d_in[4];
    const float* b_ft  = (const float*)d_in[5];
    const float* W1    = (const float*)d_in[6];
    const float* b1    = (const float*)d_in[7];
    const float* W2    = (const float*)d_in[8];
    const float* b2    = (const float*)d_in[9];
    const float* W3    = (const float*)d_in[10];
    const float* b3    = (const float*)d_in[11];
    float* out = (float*)d_out;

    dim3 tg(NF / 32, (NOUT + 31) / 32);
    transpose_wft<<<tg, dim3(32, 8)>>>(W_ft);
    nnue_row<<<NROWS, 256>>>(wf, bfeat, stm, bkt, b_ft,
                             W1, b1, W2, b2, W3, b3, out);
}